// round 8
// baseline (speedup 1.0000x reference)
#include <cuda_runtime.h>
#include <cstdint>

// Problem constants (from reference)
#define N_ATOMS   100000
#define N_PAIRS   6400000
#define NS        119
#define R_MAX     6.0f
#define PI_F      3.14159265358979323846f
#define LOG2E_F   1.4426950408889634f

#define THREADS   256
#define UNROLL    2
#define PAIRS_PER_BLOCK (THREADS * UNROLL)             // 512
#define NBLK      (N_PAIRS / PAIRS_PER_BLOCK)          // 12500 (exact)

#define TAB_BLOCKS ((NS * NS + 255) / 256)             // 56
#define PACK_BLOCKS ((N_ATOMS + 255) / 256)            // 391

// -------- device scratch (no allocations allowed) --------
// 32B-aligned table entry -> exactly one L2 sector per gather
struct __align__(32) TabA {
    float4 a;   // {pc0, pc1, pc2, pe0}
    float4 b;   // {pe1, pe2, De,  p1 }
};
__device__ float4 g_RZ[N_ATOMS];              // {x, y, z, as_float(Z)}
__device__ TabA   g_tabA[NS * NS];            // 453 KB (1 sector/entry)
__device__ float2 g_tabB[NS * NS];            // {p2, rinv} 113 KB -> L1-resident
__device__ float  g_partial[NBLK];
__device__ unsigned int g_arrived = 0;        // last-block-done counter (self-resetting)

// Fast MUFU ops via PTX (single instruction regardless of compile flags)
__device__ __forceinline__ float fex2(float x) {
    float y; asm("ex2.approx.ftz.f32 %0, %1;" : "=f"(y) : "f"(x)); return y;
}
__device__ __forceinline__ float flg2(float x) {
    float y; asm("lg2.approx.ftz.f32 %0, %1;" : "=f"(y) : "f"(x)); return y;
}
__device__ __forceinline__ float frsq(float x) {
    float y; asm("rsqrt.approx.ftz.f32 %0, %1;" : "=f"(y) : "f"(x)); return y;
}

// softplus, matches jax.nn.softplus numerics: relu(x) + log1p(exp(-|x|))
__device__ __forceinline__ float sp(float x) {
    return fmaxf(x, 0.0f) + log1pf(expf(-fabsf(x)));
}

// -------- kernel 1: build tables + pack RZ (fused) --------
__global__ void prep_kernel(const float* __restrict__ R,
                            const int* __restrict__ Z,
                            const float* __restrict__ r0,
                            const float* __restrict__ po_coeff,
                            const float* __restrict__ po_exp,
                            const float* __restrict__ De,
                            const float* __restrict__ pbe1,
                            const float* __restrict__ pbe2) {
    if (blockIdx.x < TAB_BLOCKS) {
        int e = blockIdx.x * blockDim.x + threadIdx.x;
        if (e >= NS * NS) return;
        int zi = e / NS;
        int zj = e - zi * NS;

        TabA ta;
        ta.a.x = sp(po_coeff[e * 3 + 0]);
        ta.a.y = sp(po_coeff[e * 3 + 1]);
        ta.a.z = sp(po_coeff[e * 3 + 2]);
        ta.a.w = sp(po_exp[e * 3 + 0]);
        ta.b.x = sp(po_exp[e * 3 + 1]);
        ta.b.y = sp(po_exp[e * 3 + 2]);
        ta.b.z = sp(De[e]);
        ta.b.w = pbe1[e];
        g_tabA[e] = ta;

        float r0ij = 0.5f * (sp(r0[zi]) + sp(r0[zj]));
        g_tabB[e] = make_float2(sp(pbe2[e] + 1.0f), 1.0f / r0ij);
    } else {
        int i = (blockIdx.x - TAB_BLOCKS) * blockDim.x + threadIdx.x;
        if (i >= N_ATOMS) return;
        g_RZ[i] = make_float4(R[3 * i + 0], R[3 * i + 1], R[3 * i + 2],
                              __int_as_float(Z[i]));
    }
}

// -------- warp/block reduction helper --------
__device__ __forceinline__ float warp_sum(float v) {
    #pragma unroll
    for (int o = 16; o > 0; o >>= 1)
        v += __shfl_down_sync(0xffffffffu, v, o);
    return v;
}

// streaming (evict-first) int2 load: keep L1 for RZ/tab gathers
__device__ __forceinline__ int2 ldcs_int2(const int2* p) {
    int2 v;
    asm("ld.global.cs.v2.s32 {%0, %1}, [%2];"
        : "=r"(v.x), "=r"(v.y) : "l"(p));
    return v;
}

// -------- kernel 2: main pair kernel, 2 pairs/thread, fused final reduce --------
__global__ void __launch_bounds__(THREADS)
pair_kernel(const int* __restrict__ idx, float* __restrict__ out) {
    int t = blockIdx.x * blockDim.x + threadIdx.x;   // always < N_PAIRS/2

    // coalesced streaming int2 loads: 2 pair indices per stream
    int2 iv = ldcs_int2(reinterpret_cast<const int2*>(idx) + t);
    int2 jv = ldcs_int2(reinterpret_cast<const int2*>(idx + N_PAIRS) + t);
    int ii[UNROLL] = {iv.x, iv.y};
    int jj[UNROLL] = {jv.x, jv.y};

    // front-batched RZ gathers (4 independent LDG.128)
    float4 A[UNROLL], B[UNROLL];
    #pragma unroll
    for (int k = 0; k < UNROLL; k++) {
        A[k] = g_RZ[ii[k]];
        B[k] = g_RZ[jj[k]];
    }

    // batched table loads (tabA: 1 sector each; tabB: L1-resident)
    float4 QA[UNROLL], QB[UNROLL];
    float2 QC[UNROLL];
    #pragma unroll
    for (int k = 0; k < UNROLL; k++) {
        int e = __float_as_int(A[k].w) * NS + __float_as_int(B[k].w);
        QA[k] = g_tabA[e].a;
        QB[k] = g_tabA[e].b;
        QC[k] = g_tabB[e];
    }

    float E = 0.0f;
    #pragma unroll
    for (int k = 0; k < UNROLL; k++) {
        float dx = B[k].x - A[k].x;
        float dy = B[k].y - A[k].y;
        float dz = B[k].z - A[k].z;
        float d2 = fmaf(dx, dx, fmaf(dy, dy, dz * dz));
        bool pos = d2 > 0.0f;
        float dr = pos ? d2 * frsq(d2) : 0.0f;
        float drc = fminf(dr, R_MAX);
        float cut = 0.5f * (__cosf(drc * (PI_F / R_MAX)) + 1.0f);

        float ratio = dr * QC[k].y;
        float L = flg2(ratio);                 // -inf when dr == 0
        float t0 = fex2(QA[k].w * L);
        float t1 = fex2(QB[k].x * L);
        float t2 = fex2(QB[k].y * L);
        if (!pos) { t0 = 0.0f; t1 = 0.0f; t2 = 0.0f; }   // safe_pow limit

        float e0 = fex2(-LOG2E_F * QA[k].x * t0);
        float e1 = fex2(-LOG2E_F * QA[k].y * t1);
        float e2 = fex2(-LOG2E_F * QA[k].z * t2);
        float bo = cut * (e0 + e1 + e2);

        float bp = (bo > 0.0f) ? fex2(QC[k].x * flg2(bo)) : 0.0f;
        float ef = fex2(LOG2E_F * QB[k].w * (1.0f - bp));
        float Ek = -QB[k].z * bo * ef;
        E += (ii[k] != jj[k]) ? Ek : 0.0f;     // mask padded / self pairs
    }

    // block reduction to partials (deterministic)
    __shared__ float sh[THREADS / 32];
    __shared__ bool s_last;
    float v = warp_sum(E);
    int lane = threadIdx.x & 31;
    int wid  = threadIdx.x >> 5;
    if (lane == 0) sh[wid] = v;
    __syncthreads();
    if (wid == 0) {
        v = (lane < (THREADS / 32)) ? sh[lane] : 0.0f;
        v = warp_sum(v);
        if (lane == 0) {
            g_partial[blockIdx.x] = v;
            __threadfence();                                // partial visible first
            unsigned int n = atomicAdd(&g_arrived, 1u);
            s_last = (n == NBLK - 1);
        }
    }
    __syncthreads();

    // last block performs the final deterministic reduction (fixed order)
    if (s_last) {
        float s = 0.0f;
        for (int i = threadIdx.x; i < NBLK; i += THREADS)
            s += g_partial[i];
        float w = warp_sum(s);
        if (lane == 0) sh[wid] = w;
        __syncthreads();
        if (wid == 0) {
            w = (lane < (THREADS / 32)) ? sh[lane] : 0.0f;
            w = warp_sum(w);
            if (lane == 0) {
                out[0] = w;
                g_arrived = 0;          // reset for next graph replay
            }
        }
    }
}

extern "C" void kernel_launch(void* const* d_in, const int* in_sizes, int n_in,
                              void* d_out, int out_size) {
    const float* R        = (const float*)d_in[0];
    const int*   Z        = (const int*)  d_in[1];
    const int*   idx      = (const int*)  d_in[2];
    const float* r0       = (const float*)d_in[3];
    const float* po_coeff = (const float*)d_in[4];
    const float* po_exp   = (const float*)d_in[5];
    const float* De       = (const float*)d_in[6];
    const float* pbe1     = (const float*)d_in[7];
    const float* pbe2     = (const float*)d_in[8];
    float* out = (float*)d_out;

    prep_kernel<<<TAB_BLOCKS + PACK_BLOCKS, 256>>>(R, Z, r0, po_coeff, po_exp,
                                                   De, pbe1, pbe2);
    pair_kernel<<<NBLK, THREADS>>>(idx, out);
}